// round 2
// baseline (speedup 1.0000x reference)
#include <cuda_runtime.h>

#define D 64
#define NB 1024
#define XS 68   // padded row stride (floats): 68*4B = 272B, 16B-aligned, bank-skewed

// Scratch (allocation-free rule: __device__ globals)
__device__ __align__(16) float g_Wt[8 * D * D];   // Wt[m][e*64+d] = W[m][d*64+e]

typedef unsigned long long ull;

__device__ __forceinline__ float leaky(float x) { return x >= 0.f ? x : 0.2f * x; }
__device__ __forceinline__ float avgw(int cnt)  { return cnt > 0 ? 1.0f / ((float)cnt + 1e-8f) : 0.0f; }

__device__ __forceinline__ ull pack2(float x, float y) {
    ull r; asm("mov.b64 %0, {%1, %2};" : "=l"(r) : "f"(x), "f"(y)); return r;
}
__device__ __forceinline__ float2 unpack2(ull v) {
    float2 f; asm("mov.b64 {%0, %1}, %2;" : "=f"(f.x), "=f"(f.y) : "l"(v)); return f;
}
__device__ __forceinline__ void fma2(ull& acc, ull a, ull b) {
    asm("fma.rn.f32x2 %0, %1, %2, %3;" : "=l"(acc) : "l"(a), "l"(b), "l"(acc));
}

// ---------------------------------------------------------------------------
// K0: transpose the 8 weight matrices into g_Wt (coalesced d-lane access)
// ---------------------------------------------------------------------------
__global__ void k_transpose(const float* __restrict__ w0, const float* __restrict__ w1,
                            const float* __restrict__ w2, const float* __restrict__ w3,
                            const float* __restrict__ w4, const float* __restrict__ w5,
                            const float* __restrict__ w6, const float* __restrict__ w7) {
    const float* Ws[8] = {w0, w1, w2, w3, w4, w5, w6, w7};
    int m = blockIdx.x >> 2;          // 32 blocks: 8 matrices x 4 chunks
    int part = blockIdx.x & 3;
    const float* W = Ws[m];
    int idx = part * 1024 + threadIdx.x;   // 1024 threads -> 1 elem each
    int e = idx >> 6, d = idx & 63;
    g_Wt[m * D * D + idx] = W[d * D + e];
}

// ---------------------------------------------------------------------------
// Fused dsd + usu + dot: one block (512 threads) per batch element
// ---------------------------------------------------------------------------
__global__ void __launch_bounds__(512)
k_fused(const float* __restrict__ E_s, const float* __restrict__ E_d,
        const int* __restrict__ label, const int* __restrict__ dsd_1,
        const int* __restrict__ dsd_2, const int* __restrict__ usu_1,
        const int* __restrict__ usu_2, const int* __restrict__ usu_3,
        float* __restrict__ out) {
    int b = blockIdx.x;
    int t = threadIdx.x;

    __shared__ float shA[8 * XS];     // dual-matvec input 1 (stride 68)
    __shared__ float shB[8 * XS];     // dual-matvec input 2
    __shared__ float shE[8 * XS];     // matvec outputs (emb_s1 / es1)
    __shared__ float shX[64 * XS];    // usu avg_s3 rows [64][64] (stride 68)
    __shared__ float shU[8 * D];      // u1 rows
    __shared__ float shDise[D];
    __shared__ int   shI[1024];       // usu_3 indices
    __shared__ int   shI2d[64], shI2u[64], shI1d[8], shI1u[8];
    __shared__ float sh_red[2];

    // ---- P0: index staging ----
    ((int2*)shI)[t] = ((const int2*)(usu_3 + b * 1024))[t];
    if (t < 64)                 shI2d[t]       = dsd_2[b * 64 + t];
    else if (t < 128)           shI2u[t - 64]  = usu_2[b * 64 + (t - 64)];
    else if (t < 136)           shI1d[t - 128] = dsd_1[b * 8 + (t - 128)];
    else if (t < 144)           shI1u[t - 136] = usu_1[b * 8 + (t - 136)];
    __syncthreads();

    // ---- P1+P5: all gathers (float4), slot = t>>4 in [0,32), lane16 dims ----
    {
        int slot = t >> 4, d4 = (t & 15) * 4;
        // usu_3 gathers: 2 rows per slot
#pragma unroll
        for (int rr = 0; rr < 2; ++rr) {
            int r = slot * 2 + rr;
            const int* ip = shI + r * 16;
            float4 s = make_float4(0.f, 0.f, 0.f, 0.f);
            int cnt = 0;
#pragma unroll
            for (int k = 0; k < 16; ++k) {
                int ix = ip[k];
                cnt += (ix != 0);
                float4 v = *(const float4*)(E_s + ix * D + d4);
                s.x += v.x; s.y += v.y; s.z += v.z; s.w += v.w;
            }
            float w = avgw(cnt);
            *(float4*)&shX[r * XS + d4] = make_float4(s.x * w, s.y * w, s.z * w, s.w * w);
        }
        // dsd ed gathers + es (slots 0..7) and u1 loads (slots 8..15)
        if (slot < 8) {
            int r = slot;
            float4 s = make_float4(0.f, 0.f, 0.f, 0.f);
            int cnt = 0;
#pragma unroll
            for (int h = 0; h < 8; ++h) {
                int ix = shI2d[r * 8 + h];
                cnt += (ix != 0);
                float4 v = *(const float4*)(E_d + ix * D + d4);
                s.x += v.x; s.y += v.y; s.z += v.z; s.w += v.w;
            }
            float w = avgw(cnt);
            float4 es = *(const float4*)(E_s + shI1d[r] * D + d4);
            float4 av = make_float4(s.x * w, s.y * w, s.z * w, s.w * w);
            *(float4*)&shA[r * XS + d4] = make_float4(es.x + av.x, es.y + av.y, es.z + av.z, es.w + av.w);
            *(float4*)&shB[r * XS + d4] = make_float4(av.x * es.x, av.y * es.y, av.z * es.z, av.w * es.w);
        } else if (slot < 16) {
            int r = slot - 8;
            *(float4*)&shU[r * D + d4] = *(const float4*)(E_s + shI1u[r] * D + d4);
        }
    }
    __syncthreads();

    // ---- P2: dsd matvec1 (emb_s1), dual mats W21/W22, f32x2, 128 threads ----
    if (t < 128) {
        int g = t >> 4, d4 = (t & 15) * 4;
        const float* W21t = g_Wt + 0 * D * D;
        const float* W22t = g_Wt + 1 * D * D;
        ull accL = 0ull, accH = 0ull;
#pragma unroll 8
        for (int e = 0; e < D; ++e) {
            float a = shA[g * XS + e], bb = shB[g * XS + e];
            ulonglong2 wa = *(const ulonglong2*)(W21t + e * D + d4);
            ulonglong2 wb = *(const ulonglong2*)(W22t + e * D + d4);
            ull a2 = pack2(a, a), b2 = pack2(bb, bb);
            fma2(accL, a2, wa.x); fma2(accL, b2, wb.x);
            fma2(accH, a2, wa.y); fma2(accH, b2, wb.y);
        }
        float2 lo = unpack2(accL), hi = unpack2(accH);
        *(float4*)&shE[g * XS + d4] =
            make_float4(leaky(lo.x), leaky(lo.y), leaky(hi.x), leaky(hi.y));
    }
    __syncthreads();

    // ---- P3: dsd reduce over h1 + build second matvec inputs ----
    if (t < 64) {
        float a = 0.f;
#pragma unroll
        for (int i = 0; i < 8; ++i) a += shE[i * XS + t];
        int c1 = 0;
#pragma unroll
        for (int i = 0; i < 8; ++i) c1 += (shI1d[i] != 0);
        float A = a * avgw(c1);
        float td = E_d[label[b] * D + t];
        shA[t] = A + td;
        shB[t] = A * td;
    }
    __syncthreads();

    // ---- P4: dsd matvec2 -> emb_dise ----
    if (t < 64) {
        const float* W11t = g_Wt + 2 * D * D;
        const float* W12t = g_Wt + 3 * D * D;
        float acc = 0.f;
#pragma unroll 8
        for (int e = 0; e < D; ++e)
            acc = fmaf(shA[e], W11t[e * D + t], fmaf(shB[e], W12t[e * D + t], acc));
        shDise[t] = leaky(acc);
    }
    __syncthreads();

    // ---- P6: usu eu2 GEMM (j-blocked, f32x2), 256 threads = 8g x 2jh x 16lane ----
    if (t < 256) {
        int lane16 = t & 15, jh = (t >> 4) & 1, g = t >> 5;
        int d4 = lane16 * 4;
        int rbase = g * 8 + jh * 4;
        const float* W3t = g_Wt + 4 * D * D;
        ull accL[4] = {0ull, 0ull, 0ull, 0ull};
        ull accH[4] = {0ull, 0ull, 0ull, 0ull};
#pragma unroll 4
        for (int e = 0; e < D; ++e) {
            ulonglong2 w = *(const ulonglong2*)(W3t + e * D + d4);
#pragma unroll
            for (int j = 0; j < 4; ++j) {
                float x = shX[(rbase + j) * XS + e];
                ull xx = pack2(x, x);
                fma2(accL[j], xx, w.x);
                fma2(accH[j], xx, w.y);
            }
        }
        float s0 = 0.f, s1 = 0.f, s2 = 0.f, s3 = 0.f;
#pragma unroll
        for (int j = 0; j < 4; ++j) {
            float2 lo = unpack2(accL[j]), hi = unpack2(accH[j]);
            s0 += leaky(lo.x); s1 += leaky(lo.y);
            s2 += leaky(hi.x); s3 += leaky(hi.y);
        }
        s0 += __shfl_down_sync(0xffffffffu, s0, 16);
        s1 += __shfl_down_sync(0xffffffffu, s1, 16);
        s2 += __shfl_down_sync(0xffffffffu, s2, 16);
        s3 += __shfl_down_sync(0xffffffffu, s3, 16);
        if (jh == 0) {
            int c2 = 0;
#pragma unroll
            for (int jj = 0; jj < 8; ++jj) c2 += (shI2u[g * 8 + jj] != 0);
            float w2 = avgw(c2);
            float4 u = *(float4*)&shU[g * D + d4];
            float S0 = s0 * w2, S1 = s1 * w2, S2 = s2 * w2, S3 = s3 * w2;
            *(float4*)&shA[g * XS + d4] = make_float4(u.x + S0, u.y + S1, u.z + S2, u.w + S3);
            *(float4*)&shB[g * XS + d4] = make_float4(S0 * u.x, S1 * u.y, S2 * u.z, S3 * u.w);
        }
    }
    __syncthreads();

    // ---- P7: usu es1 matvec, dual mats W21u/W22u, f32x2, 128 threads ----
    if (t < 128) {
        int g = t >> 4, d4 = (t & 15) * 4;
        const float* W21t = g_Wt + 5 * D * D;
        const float* W22t = g_Wt + 6 * D * D;
        ull accL = 0ull, accH = 0ull;
#pragma unroll 8
        for (int e = 0; e < D; ++e) {
            float a = shA[g * XS + e], bb = shB[g * XS + e];
            ulonglong2 wa = *(const ulonglong2*)(W21t + e * D + d4);
            ulonglong2 wb = *(const ulonglong2*)(W22t + e * D + d4);
            ull a2 = pack2(a, a), b2 = pack2(bb, bb);
            fma2(accL, a2, wa.x); fma2(accL, b2, wb.x);
            fma2(accH, a2, wa.y); fma2(accH, b2, wb.y);
        }
        float2 lo = unpack2(accL), hi = unpack2(accH);
        *(float4*)&shE[g * XS + d4] =
            make_float4(leaky(lo.x), leaky(lo.y), leaky(hi.x), leaky(hi.y));
    }
    __syncthreads();

    // ---- P8: reduce es1 over i (usu_1 mask) ----
    if (t < 64) {
        float a = 0.f;
#pragma unroll
        for (int i = 0; i < 8; ++i) a += shE[i * XS + t];
        int c1 = 0;
#pragma unroll
        for (int i = 0; i < 8; ++i) c1 += (shI1u[i] != 0);
        shA[t] = a * avgw(c1);
    }
    __syncthreads();

    // ---- P9: emb_user matvec + dot with emb_dise + block reduce ----
    if (t < 64) {
        const float* W1t = g_Wt + 7 * D * D;
        float acc = 0.f;
#pragma unroll 8
        for (int e = 0; e < D; ++e)
            acc = fmaf(shA[e], W1t[e * D + t], acc);
        float v = leaky(acc) * shDise[t];
#pragma unroll
        for (int o = 16; o > 0; o >>= 1)
            v += __shfl_down_sync(0xffffffffu, v, o);
        if ((t & 31) == 0) sh_red[t >> 5] = v;
    }
    __syncthreads();
    if (t == 0) out[b] = sh_red[0] + sh_red[1];
}

// ---------------------------------------------------------------------------
extern "C" void kernel_launch(void* const* d_in, const int* in_sizes, int n_in,
                              void* d_out, int out_size) {
    const float* E_s = (const float*)d_in[0];
    const float* E_d = (const float*)d_in[1];
    // weights: W_dsd_21, W_dsd_22, W_dsd_11, W_dsd_12, W_usu_3, W_usu_21, W_usu_22, W_usu_1
    k_transpose<<<32, 1024>>>((const float*)d_in[2], (const float*)d_in[3],
                              (const float*)d_in[4], (const float*)d_in[5],
                              (const float*)d_in[6], (const float*)d_in[7],
                              (const float*)d_in[8], (const float*)d_in[9]);

    k_fused<<<NB, 512>>>(E_s, E_d,
                         (const int*)d_in[10], (const int*)d_in[11], (const int*)d_in[12],
                         (const int*)d_in[13], (const int*)d_in[14], (const int*)d_in[15],
                         (float*)d_out);
}

// round 3
// speedup vs baseline: 1.9036x; 1.9036x over previous
#include <cuda_runtime.h>

#define D 64
#define NB 1024
#define XS 68   // padded smem row stride (floats)

// Scratch (allocation-free rule: __device__ globals)
__device__ __align__(16) float g_Wt[8 * D * D];    // Wt[m][e*64+d] = W[m][d*64+e]
__device__ __align__(16) float g_UA[NB * 8 * D];   // u1 + S
__device__ __align__(16) float g_UB[NB * 8 * D];   // S * u1
__device__ __align__(16) float g_dise[NB * D];     // emb_dise

typedef unsigned long long ull;

__device__ __forceinline__ float leaky(float x) { return x >= 0.f ? x : 0.2f * x; }
__device__ __forceinline__ float avgw(int cnt)  { return cnt > 0 ? 1.0f / ((float)cnt + 1e-8f) : 0.0f; }

__device__ __forceinline__ ull pack2(float x, float y) {
    ull r; asm("mov.b64 %0, {%1, %2};" : "=l"(r) : "f"(x), "f"(y)); return r;
}
__device__ __forceinline__ float2 unpack2(ull v) {
    float2 f; asm("mov.b64 {%0, %1}, %2;" : "=f"(f.x), "=f"(f.y) : "l"(v)); return f;
}
__device__ __forceinline__ void fma2(ull& acc, ull a, ull b) {
    asm("fma.rn.f32x2 %0, %1, %2, %3;" : "=l"(acc) : "l"(a), "l"(b), "l"(acc));
}

// ---------------------------------------------------------------------------
// K0: transpose the 8 weight matrices into g_Wt
// ---------------------------------------------------------------------------
__global__ void k_transpose(const float* __restrict__ w0, const float* __restrict__ w1,
                            const float* __restrict__ w2, const float* __restrict__ w3,
                            const float* __restrict__ w4, const float* __restrict__ w5,
                            const float* __restrict__ w6, const float* __restrict__ w7) {
    const float* Ws[8] = {w0, w1, w2, w3, w4, w5, w6, w7};
    int m = blockIdx.x >> 2;
    int part = blockIdx.x & 3;
    int idx = part * 1024 + threadIdx.x;
    int e = idx >> 6, d = idx & 63;
    g_Wt[m * D * D + idx] = Ws[m][d * D + e];
}

// ---------------------------------------------------------------------------
// K1: inner kernel. blocks [0, 8192): usu inner per (b,g).
//     blocks [8192, 9216): dsd full path per b.
// 128 threads = 16 lanes (4 dims each) x 8 slots.
// ---------------------------------------------------------------------------
__global__ void __launch_bounds__(128)
k_inner(const float* __restrict__ E_s, const float* __restrict__ E_d,
        const int* __restrict__ label,
        const int* __restrict__ dsd_1, const int* __restrict__ dsd_2,
        const int* __restrict__ usu_1, const int* __restrict__ usu_2,
        const int* __restrict__ usu_3) {
    int t = threadIdx.x;
    __shared__ float shX[8][XS];        // matvec input 1
    __shared__ float shY[8][XS];        // matvec input 2
    __shared__ float shP[8][8][D];      // chunk partials [chunk][row][dim]
    __shared__ float shL[8][XS];        // leaky outputs
    __shared__ int   sIdx[128];
    __shared__ int   sAux[8];

    int lane = t & 15;
    int d4 = lane * 4;

    if (blockIdx.x < NB * 8) {
        // ================= usu inner: one (b, g) per block =================
        int bg = blockIdx.x;
        sIdx[t] = usu_3[bg * 128 + t];            // [j][k] contiguous 128 ints
        if (t < 8) sAux[t] = usu_2[bg * 8 + t];
        __syncthreads();

        // gather + masked avg: row j = t>>4, 16 neighbors each
        {
            int j = t >> 4;
            const int* ip = sIdx + j * 16;
            float sx = 0.f, sy = 0.f, sz = 0.f, sw = 0.f;
            int cnt = 0;
#pragma unroll
            for (int k = 0; k < 16; ++k) {
                int ix = ip[k];
                cnt += (ix != 0);
                float4 v = *(const float4*)(E_s + ix * D + d4);
                sx += v.x; sy += v.y; sz += v.z; sw += v.w;
            }
            float w = avgw(cnt);
            *(float4*)&shX[j][d4] = make_float4(sx * w, sy * w, sz * w, sw * w);
        }
        __syncthreads();

        // matvec W3 (chunked over e): thread (lane, chunk=t>>4)
        {
            int c = t >> 4;
            const float* W3t = g_Wt + 4 * D * D;
            ull aL[8], aH[8];
#pragma unroll
            for (int j = 0; j < 8; ++j) { aL[j] = 0ull; aH[j] = 0ull; }
#pragma unroll
            for (int eo = 0; eo < 8; ++eo) {
                int e = c * 8 + eo;
                ulonglong2 w = *(const ulonglong2*)(W3t + e * D + d4);
#pragma unroll
                for (int j = 0; j < 8; ++j) {
                    float x = shX[j][e];
                    ull xx = pack2(x, x);
                    fma2(aL[j], xx, w.x);
                    fma2(aH[j], xx, w.y);
                }
            }
#pragma unroll
            for (int j = 0; j < 8; ++j) {
                float2 lo = unpack2(aL[j]), hi = unpack2(aH[j]);
                *(float4*)&shP[c][j][d4] = make_float4(lo.x, lo.y, hi.x, hi.y);
            }
        }
        __syncthreads();

        // reduce chunks + leaky: thread (lane, row j = t>>4)
        {
            int j = t >> 4;
            float sx = 0.f, sy = 0.f, sz = 0.f, sw = 0.f;
#pragma unroll
            for (int c = 0; c < 8; ++c) {
                float4 p = *(float4*)&shP[c][j][d4];
                sx += p.x; sy += p.y; sz += p.z; sw += p.w;
            }
            *(float4*)&shL[j][d4] = make_float4(leaky(sx), leaky(sy), leaky(sz), leaky(sw));
        }
        __syncthreads();

        // j-avg (usu_2 mask) + emit (u1+S, S*u1)
        if (t < 16) {
            int dd = t * 4;
            float Sx = 0.f, Sy = 0.f, Sz = 0.f, Sw = 0.f;
#pragma unroll
            for (int j = 0; j < 8; ++j) {
                float4 l = *(float4*)&shL[j][dd];
                Sx += l.x; Sy += l.y; Sz += l.z; Sw += l.w;
            }
            int c2 = 0;
#pragma unroll
            for (int j = 0; j < 8; ++j) c2 += (sAux[j] != 0);
            float w2 = avgw(c2);
            Sx *= w2; Sy *= w2; Sz *= w2; Sw *= w2;
            int iu = usu_1[bg];
            float4 u = *(const float4*)(E_s + iu * D + dd);
            *(float4*)&g_UA[bg * D + dd] = make_float4(u.x + Sx, u.y + Sy, u.z + Sz, u.w + Sw);
            *(float4*)&g_UB[bg * D + dd] = make_float4(Sx * u.x, Sy * u.y, Sz * u.z, Sw * u.w);
        }
    } else {
        // ================= dsd full path: one b per block =================
        int b = blockIdx.x - NB * 8;
        if (t < 64) sIdx[t] = dsd_2[b * 64 + t];
        else if (t < 72) sAux[t - 64] = dsd_1[b * 8 + (t - 64)];
        __syncthreads();

        // gather ed (8 nbrs) + es: row r = t>>4
        {
            int r = t >> 4;
            const int* ip = sIdx + r * 8;
            float sx = 0.f, sy = 0.f, sz = 0.f, sw = 0.f;
            int cnt = 0;
#pragma unroll
            for (int k = 0; k < 8; ++k) {
                int ix = ip[k];
                cnt += (ix != 0);
                float4 v = *(const float4*)(E_d + ix * D + d4);
                sx += v.x; sy += v.y; sz += v.z; sw += v.w;
            }
            float w = avgw(cnt);
            float4 es = *(const float4*)(E_s + sAux[r] * D + d4);
            float ax = sx * w, ay = sy * w, az = sz * w, aw = sw * w;
            *(float4*)&shX[r][d4] = make_float4(es.x + ax, es.y + ay, es.z + az, es.w + aw);
            *(float4*)&shY[r][d4] = make_float4(ax * es.x, ay * es.y, az * es.z, aw * es.w);
        }
        __syncthreads();

        // hop1 dual matvec W21/W22 (chunked)
        {
            int c = t >> 4;
            const float* W21t = g_Wt + 0 * D * D;
            const float* W22t = g_Wt + 1 * D * D;
            ull aL[8], aH[8];
#pragma unroll
            for (int r = 0; r < 8; ++r) { aL[r] = 0ull; aH[r] = 0ull; }
#pragma unroll
            for (int eo = 0; eo < 8; ++eo) {
                int e = c * 8 + eo;
                ulonglong2 wa = *(const ulonglong2*)(W21t + e * D + d4);
                ulonglong2 wb = *(const ulonglong2*)(W22t + e * D + d4);
#pragma unroll
                for (int r = 0; r < 8; ++r) {
                    ull a2 = pack2(shX[r][e], shX[r][e]);
                    ull b2 = pack2(shY[r][e], shY[r][e]);
                    fma2(aL[r], a2, wa.x); fma2(aL[r], b2, wb.x);
                    fma2(aH[r], a2, wa.y); fma2(aH[r], b2, wb.y);
                }
            }
#pragma unroll
            for (int r = 0; r < 8; ++r) {
                float2 lo = unpack2(aL[r]), hi = unpack2(aH[r]);
                *(float4*)&shP[c][r][d4] = make_float4(lo.x, lo.y, hi.x, hi.y);
            }
        }
        __syncthreads();

        // reduce + leaky -> emb_s1
        {
            int r = t >> 4;
            float sx = 0.f, sy = 0.f, sz = 0.f, sw = 0.f;
#pragma unroll
            for (int c = 0; c < 8; ++c) {
                float4 p = *(float4*)&shP[c][r][d4];
                sx += p.x; sy += p.y; sz += p.z; sw += p.w;
            }
            *(float4*)&shL[r][d4] = make_float4(leaky(sx), leaky(sy), leaky(sz), leaky(sw));
        }
        __syncthreads();

        // g-avg (dsd_1 mask) + hop2 inputs
        if (t < 16) {
            int dd = t * 4;
            float Ax = 0.f, Ay = 0.f, Az = 0.f, Aw = 0.f;
#pragma unroll
            for (int r = 0; r < 8; ++r) {
                float4 l = *(float4*)&shL[r][dd];
                Ax += l.x; Ay += l.y; Az += l.z; Aw += l.w;
            }
            int c1 = 0;
#pragma unroll
            for (int r = 0; r < 8; ++r) c1 += (sAux[r] != 0);
            float w1 = avgw(c1);
            Ax *= w1; Ay *= w1; Az *= w1; Aw *= w1;
            float4 td = *(const float4*)(E_d + label[b] * D + dd);
            *(float4*)&shX[0][dd] = make_float4(Ax + td.x, Ay + td.y, Az + td.z, Aw + td.w);
            *(float4*)&shY[0][dd] = make_float4(Ax * td.x, Ay * td.y, Az * td.z, Aw * td.w);
        }
        __syncthreads();

        // hop2 dual matvec W11/W12 (1 row, chunked)
        {
            int c = t >> 4;
            const float* W11t = g_Wt + 2 * D * D;
            const float* W12t = g_Wt + 3 * D * D;
            ull aL = 0ull, aH = 0ull;
#pragma unroll
            for (int eo = 0; eo < 8; ++eo) {
                int e = c * 8 + eo;
                ulonglong2 wa = *(const ulonglong2*)(W11t + e * D + d4);
                ulonglong2 wb = *(const ulonglong2*)(W12t + e * D + d4);
                ull a2 = pack2(shX[0][e], shX[0][e]);
                ull b2 = pack2(shY[0][e], shY[0][e]);
                fma2(aL, a2, wa.x); fma2(aL, b2, wb.x);
                fma2(aH, a2, wa.y); fma2(aH, b2, wb.y);
            }
            float2 lo = unpack2(aL), hi = unpack2(aH);
            *(float4*)&shP[c][0][d4] = make_float4(lo.x, lo.y, hi.x, hi.y);
        }
        __syncthreads();

        if (t < 16) {
            int dd = t * 4;
            float sx = 0.f, sy = 0.f, sz = 0.f, sw = 0.f;
#pragma unroll
            for (int c = 0; c < 8; ++c) {
                float4 p = *(float4*)&shP[c][0][dd];
                sx += p.x; sy += p.y; sz += p.z; sw += p.w;
            }
            *(float4*)&g_dise[b * D + dd] =
                make_float4(leaky(sx), leaky(sy), leaky(sz), leaky(sw));
        }
    }
}

// ---------------------------------------------------------------------------
// K2: final per-batch kernel: es1 matvec + i-avg + W1u matvec + dot with dise
// ---------------------------------------------------------------------------
__global__ void __launch_bounds__(128)
k_final(const int* __restrict__ usu_1, float* __restrict__ out) {
    int b = blockIdx.x;
    int t = threadIdx.x;
    __shared__ float shA[8][XS];
    __shared__ float shB[8][XS];
    __shared__ float shP[8][8][D];
    __shared__ float shE[8][XS];
    __shared__ int   sI1[8];

    int lane = t & 15;
    int d4 = lane * 4;

    // load UA/UB rows
    {
        int r = t >> 4;
        *(float4*)&shA[r][d4] = *(const float4*)&g_UA[(b * 8 + r) * D + d4];
        *(float4*)&shB[r][d4] = *(const float4*)&g_UB[(b * 8 + r) * D + d4];
    }
    if (t < 8) sI1[t] = usu_1[b * 8 + t];
    __syncthreads();

    // es1 dual matvec W21u/W22u (chunked)
    {
        int c = t >> 4;
        const float* W21t = g_Wt + 5 * D * D;
        const float* W22t = g_Wt + 6 * D * D;
        ull aL[8], aH[8];
#pragma unroll
        for (int r = 0; r < 8; ++r) { aL[r] = 0ull; aH[r] = 0ull; }
#pragma unroll
        for (int eo = 0; eo < 8; ++eo) {
            int e = c * 8 + eo;
            ulonglong2 wa = *(const ulonglong2*)(W21t + e * D + d4);
            ulonglong2 wb = *(const ulonglong2*)(W22t + e * D + d4);
#pragma unroll
            for (int r = 0; r < 8; ++r) {
                ull a2 = pack2(shA[r][e], shA[r][e]);
                ull b2 = pack2(shB[r][e], shB[r][e]);
                fma2(aL[r], a2, wa.x); fma2(aL[r], b2, wb.x);
                fma2(aH[r], a2, wa.y); fma2(aH[r], b2, wb.y);
            }
        }
#pragma unroll
        for (int r = 0; r < 8; ++r) {
            float2 lo = unpack2(aL[r]), hi = unpack2(aH[r]);
            *(float4*)&shP[c][r][d4] = make_float4(lo.x, lo.y, hi.x, hi.y);
        }
    }
    __syncthreads();

    // reduce + leaky -> es1
    {
        int r = t >> 4;
        float sx = 0.f, sy = 0.f, sz = 0.f, sw = 0.f;
#pragma unroll
        for (int c = 0; c < 8; ++c) {
            float4 p = *(float4*)&shP[c][r][d4];
            sx += p.x; sy += p.y; sz += p.z; sw += p.w;
        }
        *(float4*)&shE[r][d4] = make_float4(leaky(sx), leaky(sy), leaky(sz), leaky(sw));
    }
    __syncthreads();

    // i-avg (usu_1 mask)
    if (t < 16) {
        int dd = t * 4;
        float Tx = 0.f, Ty = 0.f, Tz = 0.f, Tw = 0.f;
#pragma unroll
        for (int r = 0; r < 8; ++r) {
            float4 l = *(float4*)&shE[r][dd];
            Tx += l.x; Ty += l.y; Tz += l.z; Tw += l.w;
        }
        int c1 = 0;
#pragma unroll
        for (int r = 0; r < 8; ++r) c1 += (sI1[r] != 0);
        float w1 = avgw(c1);
        *(float4*)&shA[0][dd] = make_float4(Tx * w1, Ty * w1, Tz * w1, Tw * w1);
    }
    __syncthreads();

    // emb_user matvec W1u (1 row, chunked)
    {
        int c = t >> 4;
        const float* W1t = g_Wt + 7 * D * D;
        ull aL = 0ull, aH = 0ull;
#pragma unroll
        for (int eo = 0; eo < 8; ++eo) {
            int e = c * 8 + eo;
            ulonglong2 w = *(const ulonglong2*)(W1t + e * D + d4);
            ull xx = pack2(shA[0][e], shA[0][e]);
            fma2(aL, xx, w.x);
            fma2(aH, xx, w.y);
        }
        float2 lo = unpack2(aL), hi = unpack2(aH);
        *(float4*)&shP[c][0][d4] = make_float4(lo.x, lo.y, hi.x, hi.y);
    }
    __syncthreads();

    // final reduce + dot with emb_dise
    if (t < 16) {
        int dd = t * 4;
        float sx = 0.f, sy = 0.f, sz = 0.f, sw = 0.f;
#pragma unroll
        for (int c = 0; c < 8; ++c) {
            float4 p = *(float4*)&shP[c][0][dd];
            sx += p.x; sy += p.y; sz += p.z; sw += p.w;
        }
        float4 dz = *(const float4*)&g_dise[b * D + dd];
        float v = leaky(sx) * dz.x + leaky(sy) * dz.y +
                  leaky(sz) * dz.z + leaky(sw) * dz.w;
        v += __shfl_down_sync(0x0000ffffu, v, 8, 16);
        v += __shfl_down_sync(0x0000ffffu, v, 4, 16);
        v += __shfl_down_sync(0x0000ffffu, v, 2, 16);
        v += __shfl_down_sync(0x0000ffffu, v, 1, 16);
        if (t == 0) out[b] = v;
    }
}

// ---------------------------------------------------------------------------
extern "C" void kernel_launch(void* const* d_in, const int* in_sizes, int n_in,
                              void* d_out, int out_size) {
    const float* E_s = (const float*)d_in[0];
    const float* E_d = (const float*)d_in[1];
    // weights: W_dsd_21, W_dsd_22, W_dsd_11, W_dsd_12, W_usu_3, W_usu_21, W_usu_22, W_usu_1
    k_transpose<<<32, 1024>>>((const float*)d_in[2], (const float*)d_in[3],
                              (const float*)d_in[4], (const float*)d_in[5],
                              (const float*)d_in[6], (const float*)d_in[7],
                              (const float*)d_in[8], (const float*)d_in[9]);

    k_inner<<<NB * 8 + NB, 128>>>(E_s, E_d,
                                  (const int*)d_in[10], (const int*)d_in[11],
                                  (const int*)d_in[12], (const int*)d_in[13],
                                  (const int*)d_in[14], (const int*)d_in[15]);

    k_final<<<NB, 128>>>((const int*)d_in[13], (float*)d_out);
}